// round 8
// baseline (speedup 1.0000x reference)
#include <cuda_runtime.h>
#include <cstdint>

// ---------------- problem constants ----------------
#define BB   16
#define DD   512
#define TT   2048
#define KK   1024
#define NN   (BB*TT)          // 32768
#define NQ   (BB*DD*TT)       // 16777216

// ---------------- tiling ----------------
#define M_TILE   128          // tokens per CTA
#define N_TILE   128          // codes per n-tile
#define NT_COUNT (KK / N_TILE)   // 8
#define D_STAGE  16           // D elems per smem stage
#define N_STAGES (DD / D_STAGE)  // 32
#define THREADS  256

// smem row stride in ull units: 128 data + 4 pad = 132 (1056B, 16B aligned;
// 132*8/4 = 264 banks = 8 mod 32 -> LDS.64 phases tile banks conflict-free)
#define ROW_LDU  132
#define TILE_BYTES (D_STAGE * ROW_LDU * 8)          // 16896 per operand
#define DYN_SMEM   (4 * TILE_BYTES)                 // 67584 (A0,A1,B0,B1)

typedef unsigned long long ull;

// ---------------- PTX helpers (arch-neutral: compute_80+) ----------------
__device__ __forceinline__ uint32_t smem_u32(const void* p) {
    uint32_t a;
    asm("{ .reg .u64 t; cvta.to.shared.u64 t, %1; cvt.u32.u64 %0, t; }" : "=r"(a) : "l"(p));
    return a;
}
#define CP_ASYNC16(dst, src) asm volatile("cp.async.cg.shared.global [%0], [%1], 16;" :: "r"(dst), "l"(src))
#define CP_COMMIT()          asm volatile("cp.async.commit_group;" ::: "memory")
#define CP_WAIT1()           asm volatile("cp.async.wait_group 1;" ::: "memory")
#define CP_WAIT0()           asm volatile("cp.async.wait_group 0;" ::: "memory")

__device__ __forceinline__ uint32_t to_tf32(float v) {
    uint32_t r;
    asm("cvt.rna.tf32.f32 %0, %1;" : "=r"(r) : "f"(v));
    return r;
}
__device__ __forceinline__ ull pack_split(float v) {
    uint32_t hi = to_tf32(v);
    uint32_t lo = to_tf32(__fsub_rn(v, __uint_as_float(hi)));
    return ((ull)lo << 32) | (ull)hi;
}
#define MMA_TF32(c0,c1,c2,c3, a0,a1,a2,a3, b0,b1) \
    asm volatile("mma.sync.aligned.m16n8k8.row.col.f32.tf32.tf32.f32 " \
        "{%0,%1,%2,%3}, {%4,%5,%6,%7}, {%8,%9}, {%0,%1,%2,%3};" \
        : "+f"(c0), "+f"(c1), "+f"(c2), "+f"(c3) \
        : "r"(a0), "r"(a1), "r"(a2), "r"(a3), "r"(b0), "r"(b1))

// ---------------- device scratch (static: allocation-free rule) ---------------
__device__ ull    g_z2[(size_t)NQ];   // 128 MB: packed tf32 (hi,lo) of z, [b][d][t]
__device__ ull    g_cb2T[DD * KK];    // 4 MB: packed split of codebook, [d][k]
__device__ float  g_cbT[DD * KK];     // gather cache [d][k]
__device__ float  g_wsq[KK];
__device__ float  g_zsq[NN];
__device__ int    g_idx[NN];
__device__ double g_loss;

// ---------------- K0a: codebook prep (wsq + transpose + split) ---------------
__global__ void prep_codebook(const float* __restrict__ cb) {
    int k   = blockIdx.x;
    int tid = threadIdx.x;      // 128
    float s = 0.f;
    for (int d = tid; d < DD; d += 128) {
        float v = cb[(size_t)k * DD + d];
        g_cbT[(size_t)d * KK + k]  = v;
        g_cb2T[(size_t)d * KK + k] = pack_split(v);
        s += v * v;
    }
    #pragma unroll
    for (int o = 16; o; o >>= 1) s += __shfl_xor_sync(0xffffffffu, s, o);
    __shared__ float ws[4];
    if ((tid & 31) == 0) ws[tid >> 5] = s;
    __syncthreads();
    if (tid == 0) {
        g_wsq[k] = (ws[0] + ws[1]) + (ws[2] + ws[3]);
        if (k == 0) g_loss = 0.0;
    }
}

// ---------------- K0b: z split (packed tf32 hi/lo) ----------------------------
__global__ void split_z(const float* __restrict__ z) {
    // grid BB*DD blocks x 256 threads; block = one (b,d) row of T
    size_t base = (size_t)blockIdx.x * TT;
    #pragma unroll
    for (int r = 0; r < TT / 256; r++) {
        int t = r * 256 + threadIdx.x;
        g_z2[base + t] = pack_split(z[base + t]);
    }
}

// ---------------- K0c: per-row |z|^2 ------------------------------------------
__global__ void compute_zsq(const float* __restrict__ z) {
    int n0 = blockIdx.x * 128;
    int b  = n0 >> 11;
    int t  = (n0 & (TT - 1)) + threadIdx.x;
    const float* zb = z + (size_t)b * DD * TT + t;
    float s0 = 0.f, s1 = 0.f, s2 = 0.f, s3 = 0.f;
    #pragma unroll 4
    for (int d = 0; d < DD; d += 4) {
        float v0 = zb[(size_t)(d + 0) * TT];
        float v1 = zb[(size_t)(d + 1) * TT];
        float v2 = zb[(size_t)(d + 2) * TT];
        float v3 = zb[(size_t)(d + 3) * TT];
        s0 = fmaf(v0, v0, s0);
        s1 = fmaf(v1, v1, s1);
        s2 = fmaf(v2, v2, s2);
        s3 = fmaf(v3, v3, s3);
    }
    g_zsq[n0 + threadIdx.x] = (s0 + s1) + (s2 + s3);
}

// ---------------- K1: 3xTF32 mma.sync GEMM + argmin (pre-split operands) ------
__global__ __launch_bounds__(THREADS)
void vq_mma(float* __restrict__ out)
{
    extern __shared__ ull dyn[];   // [A0 | A1 | B0 | B1], each D_STAGE x ROW_LDU
    __shared__ float sWsq[KK];
    __shared__ ull   sRed[M_TILE][2];

    const uint32_t dynb = smem_u32(dyn);
    int tid  = threadIdx.x;
    int wid  = tid >> 5;
    int lane = tid & 31;
    int q    = lane & 3;           // thread-in-group
    int r4   = lane >> 2;          // group id
    int warpM  = (wid & 3) * 32;   // 4 M-bands
    int warpNb = wid >> 2;         // 2 N-bands
    int warpN  = warpNb * 64;

    int n0 = blockIdx.x * M_TILE;
    int b  = n0 >> 11;                 // /TT
    int t0 = n0 & (TT - 1);
    const ull* z2b = g_z2 + (size_t)b * DD * TT + t0;

    // wsq -> smem
    #pragma unroll
    for (int i = 0; i < 4; i++) sWsq[tid + i * 256] = g_wsq[tid + i * 256];

    // per-thread row squared norms (4 rows owned in epilogue math)
    float zsqr[4];
    #pragma unroll
    for (int mi = 0; mi < 2; mi++)
        #pragma unroll
        for (int h = 0; h < 2; h++)
            zsqr[mi * 2 + h] = g_zsq[n0 + warpM + 16 * mi + 8 * h + r4];

    ull bestAll = 0xffffffffffffffffULL;   // running (distbits<<32 | idx)

    // cp.async lane decomposition: each stage tile = 16 rows x 128 ull
    // = 1024 x 16B chunks; 4 per thread
    int c_row[4], c_c2[4];
    #pragma unroll
    for (int i = 0; i < 4; i++) {
        int u = tid + i * 256;
        c_row[i] = u >> 6;              // 0..15
        c_c2[i]  = (u & 63) * 2;        // ull col, even
    }

    __syncthreads();

    #pragma unroll 1
    for (int nt = 0; nt < NT_COUNT; nt++) {
        int kb0 = nt * N_TILE;
        float acc[2][8][4];
        #pragma unroll
        for (int mi = 0; mi < 2; mi++)
            #pragma unroll
            for (int nf = 0; nf < 8; nf++)
                #pragma unroll
                for (int e = 0; e < 4; e++) acc[mi][nf][e] = 0.f;

        // ---- prologue: stage 0 -> buf 0 ----
        #pragma unroll
        for (int i = 0; i < 4; i++) {
            CP_ASYNC16(dynb + (c_row[i] * ROW_LDU + c_c2[i]) * 8,
                       z2b + (size_t)c_row[i] * TT + c_c2[i]);
            CP_ASYNC16(dynb + 2 * TILE_BYTES + (c_row[i] * ROW_LDU + c_c2[i]) * 8,
                       g_cb2T + (size_t)c_row[i] * KK + kb0 + c_c2[i]);
        }
        CP_COMMIT();

        #pragma unroll 1
        for (int s = 0; s < N_STAGES; s++) {
            int cur = s & 1;
            if (s + 1 < N_STAGES) {
                int nx = cur ^ 1;
                int d0 = (s + 1) * D_STAGE;
                #pragma unroll
                for (int i = 0; i < 4; i++) {
                    CP_ASYNC16(dynb + nx * TILE_BYTES + (c_row[i] * ROW_LDU + c_c2[i]) * 8,
                               z2b + (size_t)(d0 + c_row[i]) * TT + c_c2[i]);
                    CP_ASYNC16(dynb + (2 + nx) * TILE_BYTES + (c_row[i] * ROW_LDU + c_c2[i]) * 8,
                               g_cb2T + (size_t)(d0 + c_row[i]) * KK + kb0 + c_c2[i]);
                }
                CP_COMMIT();
                CP_WAIT1();
            } else {
                CP_WAIT0();
            }
            __syncthreads();

            const ull* Zs = dyn + cur * (TILE_BYTES / 8);
            const ull* Bs = dyn + (2 + cur) * (TILE_BYTES / 8);

            #pragma unroll
            for (int j = 0; j < 2; j++) {
                // A fragments: one LDS.64 per element, hi/lo free-unpack
                uint32_t ah[2][4], al[2][4];
                #pragma unroll
                for (int mi = 0; mi < 2; mi++) {
                    int rm = warpM + 16 * mi + r4;
                    #pragma unroll
                    for (int e = 0; e < 4; e++) {
                        int dd = 8 * j + q + (e >> 1) * 4;
                        int mm = rm + (e & 1) * 8;
                        ull v = Zs[dd * ROW_LDU + mm];
                        ah[mi][e] = (uint32_t)v;
                        al[mi][e] = (uint32_t)(v >> 32);
                    }
                }
                #pragma unroll
                for (int nf = 0; nf < 8; nf++) {
                    int nn = warpN + 8 * nf + r4;
                    ull v0 = Bs[(8 * j + q) * ROW_LDU + nn];
                    ull v1 = Bs[(8 * j + q + 4) * ROW_LDU + nn];
                    uint32_t bh0 = (uint32_t)v0, bl0 = (uint32_t)(v0 >> 32);
                    uint32_t bh1 = (uint32_t)v1, bl1 = (uint32_t)(v1 >> 32);
                    #pragma unroll
                    for (int mi = 0; mi < 2; mi++) {
                        float* c = acc[mi][nf];
                        MMA_TF32(c[0], c[1], c[2], c[3],
                                 ah[mi][0], ah[mi][1], ah[mi][2], ah[mi][3], bh0, bh1);
                        MMA_TF32(c[0], c[1], c[2], c[3],
                                 ah[mi][0], ah[mi][1], ah[mi][2], ah[mi][3], bl0, bl1);
                        MMA_TF32(c[0], c[1], c[2], c[3],
                                 al[mi][0], al[mi][1], al[mi][2], al[mi][3], bh0, bh1);
                    }
                }
            }
            __syncthreads();
        }

        // ---- epilogue: dist + argmin for this n-tile ----
        #pragma unroll
        for (int mi = 0; mi < 2; mi++) {
            #pragma unroll
            for (int h = 0; h < 2; h++) {
                int  rloc = warpM + 16 * mi + 8 * h + r4;
                float zs  = zsqr[mi * 2 + h];
                ull best  = 0xffffffffffffffffULL;
                #pragma unroll
                for (int nf = 0; nf < 8; nf++) {
                    int col = kb0 + warpN + 8 * nf + 2 * q;
                    float s0 = acc[mi][nf][2 * h + 0];
                    float s1 = acc[mi][nf][2 * h + 1];
                    float v0 = __fadd_rn(__fsub_rn(zs, __fmul_rn(2.0f, s0)), sWsq[col]);
                    float v1 = __fadd_rn(__fsub_rn(zs, __fmul_rn(2.0f, s1)), sWsq[col + 1]);
                    ull p0 = ((ull)__float_as_uint(v0) << 32) | (uint32_t)col;
                    ull p1 = ((ull)__float_as_uint(v1) << 32) | (uint32_t)(col + 1);
                    if (p0 < best) best = p0;
                    if (p1 < best) best = p1;
                }
                // quad reduce (lanes 4r..4r+3 share the same row)
                ull o1 = __shfl_xor_sync(0xffffffffu, best, 1);
                if (o1 < best) best = o1;
                ull o2 = __shfl_xor_sync(0xffffffffu, best, 2);
                if (o2 < best) best = o2;
                if (q == 0) sRed[rloc][warpNb] = best;
            }
        }
        __syncthreads();
        if (tid < M_TILE) {
            ull m0 = sRed[tid][0], m1 = sRed[tid][1];
            ull m  = m0 < m1 ? m0 : m1;
            if (m < bestAll) bestAll = m;
        }
        __syncthreads();
    }

    if (tid < M_TILE) {
        int idx = (int)(uint32_t)(bestAll & 0xffffffffULL);
        g_idx[n0 + tid] = idx;
        out[(size_t)NQ + n0 + tid] = (float)idx;
    }
}

// ---------------- K2: gather z_q, write z_q_st, loss partials ----------------
__global__ void gather_out(const float* __restrict__ z, float* __restrict__ out) {
    int bd = blockIdx.x;
    int b  = bd >> 9;
    int d  = bd & (DD - 1);
    __shared__ float row[KK];
    ((float4*)row)[threadIdx.x] = ((const float4*)(g_cbT + (size_t)d * KK))[threadIdx.x];
    __syncthreads();

    size_t base = ((size_t)b * DD + d) * TT;
    int   idxs[8];
    float zv[8];
    #pragma unroll
    for (int r = 0; r < 8; r++) {
        int t  = r * 256 + threadIdx.x;
        idxs[r] = g_idx[b * TT + t];
        zv[r]   = z[base + t];
    }
    double lsum = 0.0;
    #pragma unroll
    for (int r = 0; r < 8; r++) {
        int t    = r * 256 + threadIdx.x;
        float zq = row[idxs[r]];
        out[base + t] = __fadd_rn(zv[r], __fsub_rn(zq, zv[r]));
        float df = __fsub_rn(zq, zv[r]);
        lsum += (double)df * (double)df;
    }
    #pragma unroll
    for (int o = 16; o; o >>= 1) lsum += __shfl_xor_sync(0xffffffffu, lsum, o);
    __shared__ double red[8];
    if ((threadIdx.x & 31) == 0) red[threadIdx.x >> 5] = lsum;
    __syncthreads();
    if (threadIdx.x == 0) {
        double s = 0.0;
        #pragma unroll
        for (int i = 0; i < 8; i++) s += red[i];
        atomicAdd(&g_loss, s);
    }
}

// ---------------- K3: finalize loss ------------------------------------------
__global__ void finalize_loss(float* __restrict__ out) {
    out[(size_t)NQ + NN] = (float)(g_loss * (1.25 / (double)NQ));
}

// ---------------- launch ------------------------------------------------------
extern "C" void kernel_launch(void* const* d_in, const int* in_sizes, int n_in,
                              void* d_out, int out_size) {
    const float* z  = (const float*)d_in[0];   // [16, 512, 2048] fp32
    const float* cb = (const float*)d_in[1];   // [1024, 512] fp32
    float* out = (float*)d_out;                // [z_q_st | indices | loss]

    cudaFuncSetAttribute(vq_mma, cudaFuncAttributeMaxDynamicSharedMemorySize, DYN_SMEM);

    prep_codebook<<<KK, 128>>>(cb);
    split_z<<<BB * DD, 256>>>(z);
    compute_zsq<<<NN / 128, 128>>>(z);
    vq_mma<<<NN / M_TILE, THREADS, DYN_SMEM>>>(out);
    gather_out<<<BB * DD, 256>>>(z, out);
    finalize_loss<<<1, 1>>>(out);
}

// round 9
// speedup vs baseline: 1.0844x; 1.0844x over previous
#include <cuda_runtime.h>
#include <cstdint>

// ---------------- problem constants ----------------
#define BB   16
#define DD   512
#define TT   2048
#define KK   1024
#define NN   (BB*TT)          // 32768
#define NQ   (BB*DD*TT)       // 16777216

// ---------------- tiling ----------------
#define M_TILE   64           // tokens per CTA
#define N_TILE   64           // codes per n-tile
#define NT_COUNT (KK / N_TILE)    // 16
#define D_STAGE  32               // D elems per stage
#define STAGES_PER_NT (DD / D_STAGE)  // 16
#define TOT_STAGES (NT_COUNT * STAGES_PER_NT)  // 256
#define THREADS  256

// smem layout (bytes). A row stride 72 floats (288B): banks 8q+r4 distinct.
// B row stride 68 ull (544B): 2*68 mod 32 = 8 -> phase-conflict-free LDS.64.
#define A_SLOT   (D_STAGE * 72 * 4)      // 9216
#define B_SLOT   (D_STAGE * 68 * 8)      // 17408
#define B_BASE   (3 * A_SLOT)            // 27648
#define DYN_SMEM (B_BASE + 3 * B_SLOT)   // 79872

typedef unsigned long long ull;

// ---------------- PTX helpers (arch-neutral: compute_80+) ----------------
__device__ __forceinline__ uint32_t smem_u32(const void* p) {
    uint32_t a;
    asm("{ .reg .u64 t; cvta.to.shared.u64 t, %1; cvt.u32.u64 %0, t; }" : "=r"(a) : "l"(p));
    return a;
}
#define CP_ASYNC16(dst, src) asm volatile("cp.async.cg.shared.global [%0], [%1], 16;" :: "r"(dst), "l"(src))
#define CP_COMMIT()          asm volatile("cp.async.commit_group;" ::: "memory")
#define CP_WAIT1()           asm volatile("cp.async.wait_group 1;" ::: "memory")
#define CP_WAIT0()           asm volatile("cp.async.wait_group 0;" ::: "memory")

__device__ __forceinline__ uint32_t to_tf32(float v) {
    uint32_t r;
    asm("cvt.rna.tf32.f32 %0, %1;" : "=r"(r) : "f"(v));
    return r;
}
__device__ __forceinline__ ull pack_split(float v) {
    uint32_t hi = to_tf32(v);
    uint32_t lo = to_tf32(__fsub_rn(v, __uint_as_float(hi)));
    return ((ull)lo << 32) | (ull)hi;
}
__device__ __forceinline__ void split_tf32(float v, uint32_t& hi, uint32_t& lo) {
    hi = to_tf32(v);
    lo = to_tf32(__fsub_rn(v, __uint_as_float(hi)));
}
#define MMA_TF32(c0,c1,c2,c3, a0,a1,a2,a3, b0,b1) \
    asm volatile("mma.sync.aligned.m16n8k8.row.col.f32.tf32.tf32.f32 " \
        "{%0,%1,%2,%3}, {%4,%5,%6,%7}, {%8,%9}, {%0,%1,%2,%3};" \
        : "+f"(c0), "+f"(c1), "+f"(c2), "+f"(c3) \
        : "r"(a0), "r"(a1), "r"(a2), "r"(a3), "r"(b0), "r"(b1))

// ---------------- device scratch (static: allocation-free rule) ---------------
__device__ ull    g_cb2T[DD * KK];    // 4 MB: packed tf32 split of codebook, [d][k]
__device__ float  g_cbT[DD * KK];     // gather cache [d][k]
__device__ float  g_wsq[KK];
__device__ float  g_zsq[NN];
__device__ int    g_idx[NN];
__device__ double g_loss;

// ---------------- K0a: codebook prep (wsq + transpose + split) ---------------
__global__ void prep_codebook(const float* __restrict__ cb) {
    int k   = blockIdx.x;
    int tid = threadIdx.x;      // 128
    float s = 0.f;
    for (int d = tid; d < DD; d += 128) {
        float v = cb[(size_t)k * DD + d];
        g_cbT[(size_t)d * KK + k]  = v;
        g_cb2T[(size_t)d * KK + k] = pack_split(v);
        s += v * v;
    }
    #pragma unroll
    for (int o = 16; o; o >>= 1) s += __shfl_xor_sync(0xffffffffu, s, o);
    __shared__ float ws[4];
    if ((tid & 31) == 0) ws[tid >> 5] = s;
    __syncthreads();
    if (tid == 0) {
        g_wsq[k] = (ws[0] + ws[1]) + (ws[2] + ws[3]);
        if (k == 0) g_loss = 0.0;
    }
}

// ---------------- K0b: per-row |z|^2 ------------------------------------------
__global__ void compute_zsq(const float* __restrict__ z) {
    int n0 = blockIdx.x * 128;
    int b  = n0 >> 11;
    int t  = (n0 & (TT - 1)) + threadIdx.x;
    const float* zb = z + (size_t)b * DD * TT + t;
    float s0 = 0.f, s1 = 0.f, s2 = 0.f, s3 = 0.f;
    #pragma unroll 4
    for (int d = 0; d < DD; d += 4) {
        float v0 = zb[(size_t)(d + 0) * TT];
        float v1 = zb[(size_t)(d + 1) * TT];
        float v2 = zb[(size_t)(d + 2) * TT];
        float v3 = zb[(size_t)(d + 3) * TT];
        s0 = fmaf(v0, v0, s0);
        s1 = fmaf(v1, v1, s1);
        s2 = fmaf(v2, v2, s2);
        s3 = fmaf(v3, v3, s3);
    }
    g_zsq[n0 + threadIdx.x] = (s0 + s1) + (s2 + s3);
}

// ---------------- K1: 3xTF32 mma.sync GEMM + argmin ---------------------------
// 2 CTAs/SM, 3-stage cp.async pipeline, 1 barrier/stage, register argmin.
__global__ __launch_bounds__(THREADS, 2)
void vq_mma(const float* __restrict__ z, float* __restrict__ out)
{
    extern __shared__ char dyn[];
    __shared__ float sWsq[KK];
    __shared__ ull   sRed[M_TILE][2];

    const uint32_t dynb = smem_u32(dyn);
    int tid  = threadIdx.x;
    int wid  = tid >> 5;
    int lane = tid & 31;
    int q    = lane & 3;            // thread-in-group
    int r4   = lane >> 2;           // group id
    int warpM  = (wid & 3) * 16;    // 4 M-bands of 16
    int warpNb = wid >> 2;          // 2 N-bands
    int warpN  = warpNb * 32;

    int n0 = blockIdx.x * M_TILE;
    int b  = n0 >> 11;
    int t0 = n0 & (TT - 1);
    const float* zb = z + (size_t)b * DD * TT + t0;

    // wsq -> smem
    #pragma unroll
    for (int i = 0; i < 4; i++) sWsq[tid + i * 256] = g_wsq[tid + i * 256];

    // per-thread rows: warpM + r4 (h=0), warpM + r4 + 8 (h=1)
    float zsqr[2];
    zsqr[0] = g_zsq[n0 + warpM + r4];
    zsqr[1] = g_zsq[n0 + warpM + r4 + 8];

    ull bestA[2] = { 0xffffffffffffffffULL, 0xffffffffffffffffULL };

    float acc[4][4];
    #pragma unroll
    for (int nf = 0; nf < 4; nf++)
        #pragma unroll
        for (int e = 0; e < 4; e++) acc[nf][e] = 0.f;

    // cp.async decomposition per stage:
    // A: 32 rows x 64 floats = 512 x16B, 2/thread. B: 32 rows x 64 ull = 1024 x16B, 4/thread.
    int aRow[2], aC[2], bRow[4], bC[4];
    #pragma unroll
    for (int i = 0; i < 2; i++) {
        int u = tid + i * 256;
        aRow[i] = u >> 4;          // 0..31
        aC[i]   = u & 15;          // 16B chunk
    }
    #pragma unroll
    for (int i = 0; i < 4; i++) {
        int u = tid + i * 256;
        bRow[i] = u >> 5;          // 0..31
        bC[i]   = u & 31;          // 16B chunk (2 ull)
    }

    // stage loader: gs -> (nt, s)
    auto load_stage = [&](int gs, int slot) {
        int d0  = (gs & (STAGES_PER_NT - 1)) * D_STAGE;
        int kb0 = (gs >> 4) * N_TILE;
        uint32_t ab = dynb + slot * A_SLOT;
        uint32_t bb = dynb + B_BASE + slot * B_SLOT;
        #pragma unroll
        for (int i = 0; i < 2; i++)
            CP_ASYNC16(ab + aRow[i] * 288 + aC[i] * 16,
                       zb + (size_t)(d0 + aRow[i]) * TT + aC[i] * 4);
        #pragma unroll
        for (int i = 0; i < 4; i++)
            CP_ASYNC16(bb + bRow[i] * 544 + bC[i] * 16,
                       g_cb2T + (size_t)(d0 + bRow[i]) * KK + kb0 + bC[i] * 2);
        CP_COMMIT();
    };

    __syncthreads();   // statics ready (also covers sWsq before epilogue use)

    // prologue: stages 0,1 -> slots 0,1
    load_stage(0, 0);
    load_stage(1, 1);

    #pragma unroll 1
    for (int gs = 0; gs < TOT_STAGES; gs++) {
        if (gs >= TOT_STAGES - 2) { CP_WAIT0(); } else { CP_WAIT1(); }
        __syncthreads();   // stage gs visible to all; all threads done with gs-1
        if (gs + 2 < TOT_STAGES) load_stage(gs + 2, (gs + 2) % 3);

        int slot = gs % 3;
        const float* As = (const float*)(dyn + slot * A_SLOT);
        const ull*   Bs = (const ull*)(dyn + B_BASE + slot * B_SLOT);

        #pragma unroll
        for (int j = 0; j < 4; j++) {
            // A fragment (m16k8): split fp32 -> tf32 hi/lo in registers
            uint32_t ah[4], al[4];
            #pragma unroll
            for (int e = 0; e < 4; e++) {
                int dd = 8 * j + q + (e >> 1) * 4;
                int mm = warpM + r4 + (e & 1) * 8;
                split_tf32(As[dd * 72 + mm], ah[e], al[e]);
            }
            #pragma unroll
            for (int nf = 0; nf < 4; nf++) {
                int nn = warpN + 8 * nf + r4;
                ull v0 = Bs[(8 * j + q) * 68 + nn];
                ull v1 = Bs[(8 * j + q + 4) * 68 + nn];
                uint32_t bh0 = (uint32_t)v0, bl0 = (uint32_t)(v0 >> 32);
                uint32_t bh1 = (uint32_t)v1, bl1 = (uint32_t)(v1 >> 32);
                float* c = acc[nf];
                MMA_TF32(c[0], c[1], c[2], c[3], ah[0], ah[1], ah[2], ah[3], bh0, bh1);
                MMA_TF32(c[0], c[1], c[2], c[3], ah[0], ah[1], ah[2], ah[3], bl0, bl1);
                MMA_TF32(c[0], c[1], c[2], c[3], al[0], al[1], al[2], al[3], bh0, bh1);
            }
        }

        // n-tile boundary: epilogue in registers, no barriers
        if ((gs & (STAGES_PER_NT - 1)) == STAGES_PER_NT - 1) {
            int kb0 = (gs >> 4) * N_TILE;
            #pragma unroll
            for (int h = 0; h < 2; h++) {
                float zs = zsqr[h];
                ull best = 0xffffffffffffffffULL;
                #pragma unroll
                for (int nf = 0; nf < 4; nf++) {
                    int col = kb0 + warpN + 8 * nf + 2 * q;
                    float v0 = __fadd_rn(__fsub_rn(zs, __fmul_rn(2.0f, acc[nf][2 * h + 0])), sWsq[col]);
                    float v1 = __fadd_rn(__fsub_rn(zs, __fmul_rn(2.0f, acc[nf][2 * h + 1])), sWsq[col + 1]);
                    ull p0 = ((ull)__float_as_uint(v0) << 32) | (uint32_t)col;
                    ull p1 = ((ull)__float_as_uint(v1) << 32) | (uint32_t)(col + 1);
                    if (p0 < best) best = p0;
                    if (p1 < best) best = p1;
                }
                ull o1 = __shfl_xor_sync(0xffffffffu, best, 1);
                if (o1 < best) best = o1;
                ull o2 = __shfl_xor_sync(0xffffffffu, best, 2);
                if (o2 < best) best = o2;
                if (best < bestA[h]) bestA[h] = best;
            }
            #pragma unroll
            for (int nf = 0; nf < 4; nf++)
                #pragma unroll
                for (int e = 0; e < 4; e++) acc[nf][e] = 0.f;
        }
    }

    // final cross-warp (N-band) merge
    if (q == 0) {
        sRed[warpM + r4][warpNb]     = bestA[0];
        sRed[warpM + r4 + 8][warpNb] = bestA[1];
    }
    __syncthreads();
    if (tid < M_TILE) {
        ull m0 = sRed[tid][0], m1 = sRed[tid][1];
        ull m  = m0 < m1 ? m0 : m1;
        int idx = (int)(uint32_t)(m & 0xffffffffULL);
        g_idx[n0 + tid] = idx;
        out[(size_t)NQ + n0 + tid] = (float)idx;
    }
}

// ---------------- K2: gather z_q, write z_q_st, loss partials ----------------
__global__ void gather_out(const float* __restrict__ z, float* __restrict__ out) {
    int bd = blockIdx.x;
    int b  = bd >> 9;
    int d  = bd & (DD - 1);
    __shared__ float row[KK];
    ((float4*)row)[threadIdx.x] = ((const float4*)(g_cbT + (size_t)d * KK))[threadIdx.x];
    __syncthreads();

    size_t base = ((size_t)b * DD + d) * TT;
    int   idxs[8];
    float zv[8];
    #pragma unroll
    for (int r = 0; r < 8; r++) {
        int t  = r * 256 + threadIdx.x;
        idxs[r] = g_idx[b * TT + t];
        zv[r]   = z[base + t];
    }
    double lsum = 0.0;
    #pragma unroll
    for (int r = 0; r < 8; r++) {
        int t    = r * 256 + threadIdx.x;
        float zq = row[idxs[r]];
        out[base + t] = __fadd_rn(zv[r], __fsub_rn(zq, zv[r]));
        float df = __fsub_rn(zq, zv[r]);
        lsum += (double)df * (double)df;
    }
    #pragma unroll
    for (int o = 16; o; o >>= 1) lsum += __shfl_xor_sync(0xffffffffu, lsum, o);
    __shared__ double red[8];
    if ((threadIdx.x & 31) == 0) red[threadIdx.x >> 5] = lsum;
    __syncthreads();
    if (threadIdx.x == 0) {
        double s = 0.0;
        #pragma unroll
        for (int i = 0; i < 8; i++) s += red[i];
        atomicAdd(&g_loss, s);
    }
}

// ---------------- K3: finalize loss ------------------------------------------
__global__ void finalize_loss(float* __restrict__ out) {
    out[(size_t)NQ + NN] = (float)(g_loss * (1.25 / (double)NQ));
}

// ---------------- launch ------------------------------------------------------
extern "C" void kernel_launch(void* const* d_in, const int* in_sizes, int n_in,
                              void* d_out, int out_size) {
    const float* z  = (const float*)d_in[0];   // [16, 512, 2048] fp32
    const float* cb = (const float*)d_in[1];   // [1024, 512] fp32
    float* out = (float*)d_out;                // [z_q_st | indices | loss]

    cudaFuncSetAttribute(vq_mma, cudaFuncAttributeMaxDynamicSharedMemorySize, DYN_SMEM);

    prep_codebook<<<KK, 128>>>(cb);
    compute_zsq<<<NN / 128, 128>>>(z);
    vq_mma<<<NN / M_TILE, THREADS, DYN_SMEM>>>(z, out);
    gather_out<<<BB * DD, 256>>>(z, out);
    finalize_loss<<<1, 1>>>(out);
}

// round 10
// speedup vs baseline: 1.2516x; 1.1542x over previous
#include <cuda_runtime.h>
#include <cstdint>

// ---------------- problem constants ----------------
#define BB   16
#define DD   512
#define TT   2048
#define KK   1024
#define NN   (BB*TT)          // 32768
#define NQ   (BB*DD*TT)       // 16777216

// ---------------- tiling (R7-proven skeleton) ----------------
#define M_TILE   128
#define N_TILE   128
#define NT_COUNT (KK / N_TILE)        // 8
#define D_STAGE  32
#define STAGES_PER_NT (DD / D_STAGE)  // 16
#define TOT_STAGES (NT_COUNT * STAGES_PER_NT)  // 128
#define THREADS  256

// smem plane strides (floats):
// A [d][m]: stride 136 -> LDS bank = 8q + r4 (all 32 distinct)
// B [n][d]: stride 36  -> LDS bank = 4r4 + q (all 32 distinct)
#define A_LD 136
#define B_LD 36
#define A_PLANE (D_STAGE * A_LD * 4)   // 17408
#define B_PLANE (N_TILE * B_LD * 4)    // 18432
#define OFF_AHI 0
#define OFF_ALO A_PLANE
#define OFF_BHI (2 * A_PLANE)
#define OFF_BLO (2 * A_PLANE + B_PLANE)
#define BUF_BYTES (2 * A_PLANE + 2 * B_PLANE)   // 71680
#define DYN_SMEM  (2 * BUF_BYTES)               // 143360

typedef unsigned long long ull;

// ---------------- PTX helpers (arch-neutral: compute_80+) ----------------
__device__ __forceinline__ uint32_t smem_u32(const void* p) {
    uint32_t a;
    asm("{ .reg .u64 t; cvta.to.shared.u64 t, %1; cvt.u32.u64 %0, t; }" : "=r"(a) : "l"(p));
    return a;
}
#define CP_ASYNC16(dst, src) asm volatile("cp.async.cg.shared.global [%0], [%1], 16;" :: "r"(dst), "l"(src))
#define CP_COMMIT()          asm volatile("cp.async.commit_group;" ::: "memory")
#define CP_WAIT1()           asm volatile("cp.async.wait_group 1;" ::: "memory")
#define CP_WAIT0()           asm volatile("cp.async.wait_group 0;" ::: "memory")

__device__ __forceinline__ uint32_t to_tf32(float v) {
    uint32_t r;
    asm("cvt.rna.tf32.f32 %0, %1;" : "=r"(r) : "f"(v));
    return r;
}
__device__ __forceinline__ void split_tf32(float v, float& hi, float& lo) {
    uint32_t h = to_tf32(v);
    hi = __uint_as_float(h);
    lo = __uint_as_float(to_tf32(__fsub_rn(v, hi)));
}
#define MMA_TF32(c0,c1,c2,c3, a0,a1,a2,a3, b0,b1) \
    asm volatile("mma.sync.aligned.m16n8k8.row.col.f32.tf32.tf32.f32 " \
        "{%0,%1,%2,%3}, {%4,%5,%6,%7}, {%8,%9}, {%0,%1,%2,%3};" \
        : "+f"(c0), "+f"(c1), "+f"(c2), "+f"(c3) \
        : "r"(a0), "r"(a1), "r"(a2), "r"(a3), "r"(b0), "r"(b1))

// ---------------- device scratch (static: allocation-free rule) ---------------
__device__ float  g_zHi[(size_t)NQ];   // 64 MB: tf32-hi plane of z, [b][d][t]
__device__ float  g_zLo[(size_t)NQ];   // 64 MB: tf32 residual plane
__device__ float  g_cbHi[KK * DD];     // 2 MB: [k][d]
__device__ float  g_cbLo[KK * DD];     // 2 MB
__device__ float  g_cbT[DD * KK];      // gather cache [d][k]
__device__ float  g_wsq[KK];
__device__ float  g_zsq[NN];
__device__ int    g_idx[NN];
__device__ double g_loss;

// ---------------- K0a: codebook prep (wsq + transpose + plane split) ---------
__global__ void prep_codebook(const float* __restrict__ cb) {
    int k   = blockIdx.x;
    int tid = threadIdx.x;      // 128
    float s = 0.f;
    for (int d = tid; d < DD; d += 128) {
        float v = cb[(size_t)k * DD + d];
        g_cbT[(size_t)d * KK + k] = v;
        float hi, lo;
        split_tf32(v, hi, lo);
        g_cbHi[(size_t)k * DD + d] = hi;
        g_cbLo[(size_t)k * DD + d] = lo;
        s += v * v;
    }
    #pragma unroll
    for (int o = 16; o; o >>= 1) s += __shfl_xor_sync(0xffffffffu, s, o);
    __shared__ float ws[4];
    if ((tid & 31) == 0) ws[tid >> 5] = s;
    __syncthreads();
    if (tid == 0) {
        g_wsq[k] = (ws[0] + ws[1]) + (ws[2] + ws[3]);
        if (k == 0) g_loss = 0.0;
    }
}

// ---------------- K0b: z plane split ------------------------------------------
__global__ void split_z(const float* __restrict__ z) {
    // grid BB*DD, 256 threads; thread handles 8 consecutive t
    size_t base = (size_t)blockIdx.x * TT;
    int t = threadIdx.x * 8;
    float4 v0 = *(const float4*)(z + base + t);
    float4 v1 = *(const float4*)(z + base + t + 4);
    float4 h0, l0, h1, l1;
    split_tf32(v0.x, h0.x, l0.x); split_tf32(v0.y, h0.y, l0.y);
    split_tf32(v0.z, h0.z, l0.z); split_tf32(v0.w, h0.w, l0.w);
    split_tf32(v1.x, h1.x, l1.x); split_tf32(v1.y, h1.y, l1.y);
    split_tf32(v1.z, h1.z, l1.z); split_tf32(v1.w, h1.w, l1.w);
    *(float4*)(g_zHi + base + t)     = h0;
    *(float4*)(g_zHi + base + t + 4) = h1;
    *(float4*)(g_zLo + base + t)     = l0;
    *(float4*)(g_zLo + base + t + 4) = l1;
}

// ---------------- K0c: per-row |z|^2 ------------------------------------------
__global__ void compute_zsq(const float* __restrict__ z) {
    int n0 = blockIdx.x * 128;
    int b  = n0 >> 11;
    int t  = (n0 & (TT - 1)) + threadIdx.x;
    const float* zb = z + (size_t)b * DD * TT + t;
    float s0 = 0.f, s1 = 0.f, s2 = 0.f, s3 = 0.f;
    #pragma unroll 4
    for (int d = 0; d < DD; d += 4) {
        float v0 = zb[(size_t)(d + 0) * TT];
        float v1 = zb[(size_t)(d + 1) * TT];
        float v2 = zb[(size_t)(d + 2) * TT];
        float v3 = zb[(size_t)(d + 3) * TT];
        s0 = fmaf(v0, v0, s0);
        s1 = fmaf(v1, v1, s1);
        s2 = fmaf(v2, v2, s2);
        s3 = fmaf(v3, v3, s3);
    }
    g_zsq[n0 + threadIdx.x] = (s0 + s1) + (s2 + s3);
}

// ---------------- K1: 3xTF32 mma.sync GEMM + argmin (plane-split) -------------
__global__ __launch_bounds__(THREADS)
void vq_mma(float* __restrict__ out)
{
    extern __shared__ char dyn[];
    __shared__ float sWsq[KK];
    __shared__ ull   sRed[M_TILE][2];

    const uint32_t dynb = smem_u32(dyn);
    int tid  = threadIdx.x;
    int lane = tid & 31;
    int wid  = tid >> 5;
    int q    = lane & 3;
    int r4   = lane >> 2;
    int warpM  = (wid & 3) * 32;   // 4 M-bands of 32
    int warpNb = wid >> 2;         // 2 N-bands
    int warpN  = warpNb * 64;

    int n0 = blockIdx.x * M_TILE;
    int b  = n0 >> 11;
    int t0 = n0 & (TT - 1);
    size_t zoff = (size_t)b * DD * TT + t0;

    #pragma unroll
    for (int i = 0; i < 4; i++) sWsq[tid + i * 256] = g_wsq[tid + i * 256];

    float zsqr[4];     // (mi, h) rows
    #pragma unroll
    for (int mi = 0; mi < 2; mi++)
        #pragma unroll
        for (int h = 0; h < 2; h++)
            zsqr[mi * 2 + h] = g_zsq[n0 + warpM + 16 * mi + 8 * h + r4];

    ull bestA[4] = { ~0ull, ~0ull, ~0ull, ~0ull };

    float acc[2][8][4];
    #pragma unroll
    for (int mi = 0; mi < 2; mi++)
        #pragma unroll
        for (int nf = 0; nf < 8; nf++)
            #pragma unroll
            for (int e = 0; e < 4; e++) acc[mi][nf][e] = 0.f;

    // cp.async decomposition: per plane 1024 x16B chunks, 4/thread
    int aRow[4], aC[4], bN[4], bCd[4];
    #pragma unroll
    for (int i = 0; i < 4; i++) {
        int u = tid + i * 256;
        aRow[i] = u >> 5;          // 0..31  (d row)
        aC[i]   = u & 31;          // 16B chunk along m
        bN[i]   = u >> 3;          // 0..127 (n row)
        bCd[i]  = u & 7;           // 16B chunk along d
    }

    auto load_stage = [&](int gs, int buf) {
        int d0  = (gs & (STAGES_PER_NT - 1)) * D_STAGE;
        int kb0 = (gs >> 4) * N_TILE;
        uint32_t bb = dynb + buf * BUF_BYTES;
        #pragma unroll
        for (int i = 0; i < 4; i++) {
            uint32_t adst = aRow[i] * (A_LD * 4) + aC[i] * 16;
            const float* asrc = g_zHi + zoff + (size_t)(d0 + aRow[i]) * TT + aC[i] * 4;
            CP_ASYNC16(bb + OFF_AHI + adst, asrc);
            CP_ASYNC16(bb + OFF_ALO + adst, g_zLo + (asrc - g_zHi));
            uint32_t bdst = bN[i] * (B_LD * 4) + bCd[i] * 16;
            size_t bsrc = (size_t)(kb0 + bN[i]) * DD + d0 + bCd[i] * 4;
            CP_ASYNC16(bb + OFF_BHI + bdst, g_cbHi + bsrc);
            CP_ASYNC16(bb + OFF_BLO + bdst, g_cbLo + bsrc);
        }
        CP_COMMIT();
    };

    __syncthreads();   // sWsq ready
    load_stage(0, 0);

    #pragma unroll 1
    for (int gs = 0; gs < TOT_STAGES; gs++) {
        int cur = gs & 1;
        if (gs + 1 < TOT_STAGES) { load_stage(gs + 1, cur ^ 1); CP_WAIT1(); }
        else                     { CP_WAIT0(); }
        __syncthreads();   // stage gs visible; prior reads of buf cur done

        const uint32_t* AsHi = (const uint32_t*)(dyn + cur * BUF_BYTES + OFF_AHI);
        const uint32_t* AsLo = (const uint32_t*)(dyn + cur * BUF_BYTES + OFF_ALO);
        const uint32_t* BsHi = (const uint32_t*)(dyn + cur * BUF_BYTES + OFF_BHI);
        const uint32_t* BsLo = (const uint32_t*)(dyn + cur * BUF_BYTES + OFF_BLO);

        #pragma unroll
        for (int j = 0; j < 4; j++) {
            uint32_t ah[2][4], al[2][4];
            #pragma unroll
            for (int mi = 0; mi < 2; mi++) {
                int rm = warpM + 16 * mi + r4;
                #pragma unroll
                for (int e = 0; e < 4; e++) {
                    int dd = 8 * j + q + (e >> 1) * 4;
                    int mm = rm + (e & 1) * 8;
                    ah[mi][e] = AsHi[dd * A_LD + mm];
                    al[mi][e] = AsLo[dd * A_LD + mm];
                }
            }
            #pragma unroll
            for (int nf = 0; nf < 8; nf++) {
                int nn = warpN + 8 * nf + r4;
                uint32_t bh0 = BsHi[nn * B_LD + 8 * j + q];
                uint32_t bh1 = BsHi[nn * B_LD + 8 * j + q + 4];
                uint32_t bl0 = BsLo[nn * B_LD + 8 * j + q];
                uint32_t bl1 = BsLo[nn * B_LD + 8 * j + q + 4];
                #pragma unroll
                for (int mi = 0; mi < 2; mi++) {
                    float* c = acc[mi][nf];
                    MMA_TF32(c[0], c[1], c[2], c[3],
                             ah[mi][0], ah[mi][1], ah[mi][2], ah[mi][3], bh0, bh1);
                    MMA_TF32(c[0], c[1], c[2], c[3],
                             ah[mi][0], ah[mi][1], ah[mi][2], ah[mi][3], bl0, bl1);
                    MMA_TF32(c[0], c[1], c[2], c[3],
                             al[mi][0], al[mi][1], al[mi][2], al[mi][3], bh0, bh1);
                }
            }
        }

        // n-tile boundary: register epilogue (no barriers)
        if ((gs & (STAGES_PER_NT - 1)) == STAGES_PER_NT - 1) {
            int kb0 = (gs >> 4) * N_TILE;
            #pragma unroll
            for (int mi = 0; mi < 2; mi++) {
                #pragma unroll
                for (int h = 0; h < 2; h++) {
                    float zs = zsqr[mi * 2 + h];
                    ull best = ~0ull;
                    #pragma unroll
                    for (int nf = 0; nf < 8; nf++) {
                        int col = kb0 + warpN + 8 * nf + 2 * q;
                        float v0 = __fadd_rn(__fsub_rn(zs, __fmul_rn(2.0f, acc[mi][nf][2 * h + 0])), sWsq[col]);
                        float v1 = __fadd_rn(__fsub_rn(zs, __fmul_rn(2.0f, acc[mi][nf][2 * h + 1])), sWsq[col + 1]);
                        ull p0 = ((ull)__float_as_uint(v0) << 32) | (uint32_t)col;
                        ull p1 = ((ull)__float_as_uint(v1) << 32) | (uint32_t)(col + 1);
                        if (p0 < best) best = p0;
                        if (p1 < best) best = p1;
                    }
                    ull o1 = __shfl_xor_sync(0xffffffffu, best, 1);
                    if (o1 < best) best = o1;
                    ull o2 = __shfl_xor_sync(0xffffffffu, best, 2);
                    if (o2 < best) best = o2;
                    if (best < bestA[mi * 2 + h]) bestA[mi * 2 + h] = best;
                }
            }
            #pragma unroll
            for (int mi = 0; mi < 2; mi++)
                #pragma unroll
                for (int nf = 0; nf < 8; nf++)
                    #pragma unroll
                    for (int e = 0; e < 4; e++) acc[mi][nf][e] = 0.f;
        }
        __syncthreads();   // release buf cur for gs+2's loads
    }

    if (q == 0) {
        #pragma unroll
        for (int mi = 0; mi < 2; mi++)
            #pragma unroll
            for (int h = 0; h < 2; h++)
                sRed[warpM + 16 * mi + 8 * h + r4][warpNb] = bestA[mi * 2 + h];
    }
    __syncthreads();
    if (tid < M_TILE) {
        ull m0 = sRed[tid][0], m1 = sRed[tid][1];
        ull m  = m0 < m1 ? m0 : m1;
        int idx = (int)(uint32_t)(m & 0xffffffffULL);
        g_idx[n0 + tid] = idx;
        out[(size_t)NQ + n0 + tid] = (float)idx;
    }
}

// ---------------- K2: gather z_q, write z_q_st, loss (vectorized) -------------
__global__ void gather_out(const float* __restrict__ z, float* __restrict__ out) {
    int bd = blockIdx.x;
    int b  = bd >> 9;
    int d  = bd & (DD - 1);
    __shared__ float row[KK];
    ((float4*)row)[threadIdx.x] = ((const float4*)(g_cbT + (size_t)d * KK))[threadIdx.x];
    __syncthreads();

    size_t base = ((size_t)b * DD + d) * TT;
    int t = threadIdx.x * 8;
    int4  i0 = *(const int4*)(g_idx + b * TT + t);
    int4  i1 = *(const int4*)(g_idx + b * TT + t + 4);
    float4 z0 = *(const float4*)(z + base + t);
    float4 z1 = *(const float4*)(z + base + t + 4);

    float4 o0, o1;
    double lsum = 0.0;
    {
        float zq, df;
        zq = row[i0.x]; o0.x = __fadd_rn(z0.x, __fsub_rn(zq, z0.x)); df = __fsub_rn(zq, z0.x); lsum += (double)df * df;
        zq = row[i0.y]; o0.y = __fadd_rn(z0.y, __fsub_rn(zq, z0.y)); df = __fsub_rn(zq, z0.y); lsum += (double)df * df;
        zq = row[i0.z]; o0.z = __fadd_rn(z0.z, __fsub_rn(zq, z0.z)); df = __fsub_rn(zq, z0.z); lsum += (double)df * df;
        zq = row[i0.w]; o0.w = __fadd_rn(z0.w, __fsub_rn(zq, z0.w)); df = __fsub_rn(zq, z0.w); lsum += (double)df * df;
        zq = row[i1.x]; o1.x = __fadd_rn(z1.x, __fsub_rn(zq, z1.x)); df = __fsub_rn(zq, z1.x); lsum += (double)df * df;
        zq = row[i1.y]; o1.y = __fadd_rn(z1.y, __fsub_rn(zq, z1.y)); df = __fsub_rn(zq, z1.y); lsum += (double)df * df;
        zq = row[i1.z]; o1.z = __fadd_rn(z1.z, __fsub_rn(zq, z1.z)); df = __fsub_rn(zq, z1.z); lsum += (double)df * df;
        zq = row[i1.w]; o1.w = __fadd_rn(z1.w, __fsub_rn(zq, z1.w)); df = __fsub_rn(zq, z1.w); lsum += (double)df * df;
    }
    *(float4*)(out + base + t)     = o0;
    *(float4*)(out + base + t + 4) = o1;

    #pragma unroll
    for (int o = 16; o; o >>= 1) lsum += __shfl_xor_sync(0xffffffffu, lsum, o);
    __shared__ double red[8];
    if ((threadIdx.x & 31) == 0) red[threadIdx.x >> 5] = lsum;
    __syncthreads();
    if (threadIdx.x == 0) {
        double s = 0.0;
        #pragma unroll
        for (int i = 0; i < 8; i++) s += red[i];
        atomicAdd(&g_loss, s);
    }
}

// ---------------- K3: finalize loss ------------------------------------------
__global__ void finalize_loss(float* __restrict__ out) {
    out[(size_t)NQ + NN] = (float)(g_loss * (1.25 / (double)NQ));
}

// ---------------- launch ------------------------------------------------------
extern "C" void kernel_launch(void* const* d_in, const int* in_sizes, int n_in,
                              void* d_out, int out_size) {
    const float* z  = (const float*)d_in[0];   // [16, 512, 2048] fp32
    const float* cb = (const float*)d_in[1];   // [1024, 512] fp32
    float* out = (float*)d_out;                // [z_q_st | indices | loss]

    cudaFuncSetAttribute(vq_mma, cudaFuncAttributeMaxDynamicSharedMemorySize, DYN_SMEM);

    prep_codebook<<<KK, 128>>>(cb);
    split_z<<<BB * DD, 256>>>(z);
    compute_zsq<<<NN / 128, 128>>>(z);
    vq_mma<<<NN / M_TILE, THREADS, DYN_SMEM>>>(out);
    gather_out<<<BB * DD, 256>>>(z, out);
    finalize_loss<<<1, 1>>>(out);
}